// round 1
// baseline (speedup 1.0000x reference)
#include <cuda_runtime.h>
#include <cstdint>

// ---------------- problem constants ----------------
#define BB 2
#define SS 1024
#define TT (BB*SS)      // 2048 tokens
#define HID 2880
#define HQ 64
#define HKV 8
#define DD 64
#define GG (HQ/HKV)     // 8
#define WW 128
#define QSZ (HQ*DD)     // 4096
#define KVSZ (HKV*DD)   // 512
#define SCALE 0.125f
#define THETA 150000.0f

// ---------------- scratch (no allocation allowed) ----------------
__device__ float g_q[TT*QSZ];
__device__ float g_k[TT*KVSZ];
__device__ float g_v[TT*KVSZ];
__device__ float g_att[TT*QSZ];

// ---------------- SGEMM: C[M,N] = A[M,K] @ B[K,N] + bias[N] ----------------
// 128x128 tile, BK=8, 256 threads, 8x8 per-thread microtile.
__global__ __launch_bounds__(256) void sgemm_bias(
    const float* __restrict__ A, const float* __restrict__ Bm,
    const float* __restrict__ bias, float* __restrict__ C,
    int M, int N, int K)
{
    __shared__ float As[8][128];
    __shared__ float Bs[8][128];

    const int tid = threadIdx.x;
    const int bm = blockIdx.y * 128;
    const int bn = blockIdx.x * 128;

    const int tx = tid & 15;       // 16 thread cols
    const int ty = tid >> 4;       // 16 thread rows

    // A tile load mapping: 128 rows x 8 k, float4 per thread
    const int arow = tid >> 1;
    const int acol = (tid & 1) * 4;
    // B tile load mapping: 8 k x 128 n, float4 per thread
    const int brow = tid >> 5;
    const int bcol = (tid & 31) * 4;

    float acc[8][8];
    #pragma unroll
    for (int i = 0; i < 8; i++)
        #pragma unroll
        for (int j = 0; j < 8; j++) acc[i][j] = 0.f;

    for (int k0 = 0; k0 < K; k0 += 8) {
        float4 av = make_float4(0.f,0.f,0.f,0.f);
        if (bm + arow < M)
            av = *(const float4*)&A[(size_t)(bm + arow) * K + k0 + acol];
        As[acol+0][arow] = av.x;
        As[acol+1][arow] = av.y;
        As[acol+2][arow] = av.z;
        As[acol+3][arow] = av.w;

        float4 bv = make_float4(0.f,0.f,0.f,0.f);
        if (bn + bcol < N)   // N is always a multiple of 4
            bv = *(const float4*)&Bm[(size_t)(k0 + brow) * N + bn + bcol];
        *(float4*)&Bs[brow][bcol] = bv;

        __syncthreads();

        #pragma unroll
        for (int kk = 0; kk < 8; kk++) {
            float ar[8], br[8];
            *(float4*)&ar[0] = *(const float4*)&As[kk][ty*8];
            *(float4*)&ar[4] = *(const float4*)&As[kk][ty*8+4];
            *(float4*)&br[0] = *(const float4*)&Bs[kk][tx*8];
            *(float4*)&br[4] = *(const float4*)&Bs[kk][tx*8+4];
            #pragma unroll
            for (int i = 0; i < 8; i++)
                #pragma unroll
                for (int j = 0; j < 8; j++)
                    acc[i][j] += ar[i] * br[j];
        }
        __syncthreads();
    }

    #pragma unroll
    for (int i = 0; i < 8; i++) {
        int row = bm + ty*8 + i;
        if (row >= M) continue;
        #pragma unroll
        for (int j = 0; j < 8; j++) {
            int col = bn + tx*8 + j;
            if (col < N)
                C[(size_t)row * N + col] = acc[i][j] + bias[col];
        }
    }
}

// ---------------- NeoX RoPE (in place) ----------------
__global__ void rope_kernel(float* __restrict__ x, const int* __restrict__ pos,
                            int T, int H)
{
    int idx = blockIdx.x * blockDim.x + threadIdx.x;
    const int half = DD/2;              // 32
    int total = T * H * half;
    if (idx >= total) return;
    int j = idx & 31;
    int h = (idx >> 5) % H;
    int t = idx / (half * H);

    float inv = powf(THETA, -(float)j / 32.0f);
    float ang = (float)pos[t] * inv;
    float c, s;
    sincosf(ang, &s, &c);

    float* base = x + ((size_t)t * H + h) * DD;
    float x1 = base[j];
    float x2 = base[j + half];
    base[j]        = x1 * c - x2 * s;
    base[j + half] = x1 * s + x2 * c;
}

// ---------------- sliding-window GQA attention ----------------
// grid: (HKV, S, B), 128 threads. One block handles the 8 query heads that
// share one kv head for one token. K/V window (129 x 64) staged in smem.
#define KVPAD 65
#define SCPAD 132
#define SM_KS 0
#define SM_VS (129*KVPAD)
#define SM_QS (2*129*KVPAD)
#define SM_SC (2*129*KVPAD + GG*DD)
#define SM_FLOATS (2*129*KVPAD + GG*DD + GG*SCPAD)

__global__ __launch_bounds__(128) void attn_kernel(float* __restrict__ out)
{
    extern __shared__ float sm[];
    float* Ks = sm + SM_KS;   // [129][65]
    float* Vs = sm + SM_VS;   // [129][65]
    float* qs = sm + SM_QS;   // [8][64]
    float* sc = sm + SM_SC;   // [8][132]

    const int kh = blockIdx.x;
    const int i  = blockIdx.y;
    const int b  = blockIdx.z;
    const int t  = b * SS + i;
    const int tid = threadIdx.x;

    // stage K/V window
    for (int idx = tid; idx < 129 * DD; idx += 128) {
        int w = idx >> 6, d = idx & 63;
        int p = i - WW + w;
        float kv = 0.f, vv = 0.f;
        if (p >= 0) {
            size_t off = ((size_t)(b * SS + p) * HKV + kh) * DD + d;
            kv = g_k[off];
            vv = g_v[off];
        }
        Ks[w * KVPAD + d] = kv;
        Vs[w * KVPAD + d] = vv;
    }
    // stage Q (8 heads)
    for (int idx = tid; idx < GG * DD; idx += 128) {
        int g = idx >> 6, d = idx & 63;
        qs[idx] = g_q[((size_t)t * HQ + kh * GG + g) * DD + d];
    }
    __syncthreads();

    // scores
    for (int idx = tid; idx < GG * 129; idx += 128) {
        int g = idx / 129, w = idx % 129;
        const float* qp = &qs[g * DD];
        const float* kp = &Ks[w * KVPAD];
        float s = 0.f;
        #pragma unroll 16
        for (int d = 0; d < DD; d++) s += qp[d] * kp[d];
        int p = i - WW + w;
        sc[g * SCPAD + w] = (p >= 0) ? s * SCALE : -1e30f;
    }
    __syncthreads();

    // softmax: 4 warps, 2 rows each
    const int warp = tid >> 5, lane = tid & 31;
    for (int g = warp; g < GG; g += 4) {
        float m = -1e30f;
        for (int w = lane; w < 129; w += 32) m = fmaxf(m, sc[g * SCPAD + w]);
        #pragma unroll
        for (int o = 16; o; o >>= 1) m = fmaxf(m, __shfl_xor_sync(0xffffffffu, m, o));
        float sum = 0.f;
        for (int w = lane; w < 129; w += 32) {
            float e = __expf(sc[g * SCPAD + w] - m);
            sc[g * SCPAD + w] = e;
            sum += e;
        }
        #pragma unroll
        for (int o = 16; o; o >>= 1) sum += __shfl_xor_sync(0xffffffffu, sum, o);
        float inv = 1.f / sum;
        for (int w = lane; w < 129; w += 32) sc[g * SCPAD + w] *= inv;
    }
    __syncthreads();

    // output: o[g][d] = sum_w p[g][w] * V[w][d]
    for (int idx = tid; idx < GG * DD; idx += 128) {
        int g = idx >> 6, d = idx & 63;
        const float* pr = &sc[g * SCPAD];
        const float* vp = &Vs[d];
        float o = 0.f;
        #pragma unroll 16
        for (int w = 0; w < 129; w++) o += pr[w] * vp[w * KVPAD];
        out[((size_t)t * HQ + kh * GG + g) * DD + d] = o;
    }
}

// ---------------- launch ----------------
extern "C" void kernel_launch(void* const* d_in, const int* in_sizes, int n_in,
                              void* d_out, int out_size)
{
    const float* hs = (const float*)d_in[0];
    const int*  pos = (const int*)  d_in[1];
    const float* Wq = (const float*)d_in[2];
    const float* bq = (const float*)d_in[3];
    const float* Wk = (const float*)d_in[4];
    const float* bk = (const float*)d_in[5];
    const float* Wv = (const float*)d_in[6];
    const float* bv = (const float*)d_in[7];
    const float* Wo = (const float*)d_in[8];
    const float* bo = (const float*)d_in[9];
    float* out = (float*)d_out;

    float *q, *k, *v, *att;
    cudaGetSymbolAddress((void**)&q,   g_q);
    cudaGetSymbolAddress((void**)&k,   g_k);
    cudaGetSymbolAddress((void**)&v,   g_v);
    cudaGetSymbolAddress((void**)&att, g_att);

    // QKV projections
    {
        dim3 gq((QSZ + 127) / 128, (TT + 127) / 128);
        sgemm_bias<<<gq, 256>>>(hs, Wq, bq, q, TT, QSZ, HID);
        dim3 gk((KVSZ + 127) / 128, (TT + 127) / 128);
        sgemm_bias<<<gk, 256>>>(hs, Wk, bk, k, TT, KVSZ, HID);
        sgemm_bias<<<gk, 256>>>(hs, Wv, bv, v, TT, KVSZ, HID);
    }

    // RoPE on q and k
    {
        int tq = TT * HQ * (DD/2);
        rope_kernel<<<(tq + 255) / 256, 256>>>(q, pos, TT, HQ);
        int tk = TT * HKV * (DD/2);
        rope_kernel<<<(tk + 255) / 256, 256>>>(k, pos, TT, HKV);
    }

    // attention
    {
        size_t smem = SM_FLOATS * sizeof(float);
        cudaFuncSetAttribute(attn_kernel, cudaFuncAttributeMaxDynamicSharedMemorySize, (int)smem);
        dim3 ga(HKV, SS, BB);
        attn_kernel<<<ga, 128, smem>>>(att);
    }

    // output projection
    {
        dim3 go((HID + 127) / 128, (TT + 127) / 128);
        sgemm_bias<<<go, 256>>>(att, Wo, bo, out, TT, HID, QSZ);
    }
}

// round 2
// speedup vs baseline: 1.4813x; 1.4813x over previous
#include <cuda_runtime.h>
#include <cstdint>

// ---------------- problem constants ----------------
#define BB 2
#define SS 1024
#define TT (BB*SS)      // 2048 tokens
#define HID 2880
#define HQ 64
#define HKV 8
#define DD 64
#define GG (HQ/HKV)     // 8
#define WW 128
#define QSZ (HQ*DD)     // 4096
#define KVSZ (HKV*DD)   // 512
#define SCALE 0.125f
#define THETA 150000.0f

// ---------------- scratch (no allocation allowed) ----------------
__device__ float g_q[TT*QSZ];
__device__ float g_k[TT*KVSZ];
__device__ float g_v[TT*KVSZ];
__device__ float g_att[TT*QSZ];

// ---------------- TF32 helpers ----------------
__device__ __forceinline__ uint32_t f2tf32(float x) {
    uint32_t r;
    asm("cvt.rna.tf32.f32 %0, %1;" : "=r"(r) : "f"(x));
    return r;
}

__device__ __forceinline__ void mma_tf32(float c[4], const uint32_t a[4], const uint32_t b[2]) {
    asm volatile(
        "mma.sync.aligned.m16n8k8.row.col.f32.tf32.tf32.f32 "
        "{%0,%1,%2,%3}, {%4,%5,%6,%7}, {%8,%9}, {%0,%1,%2,%3};\n"
        : "+f"(c[0]), "+f"(c[1]), "+f"(c[2]), "+f"(c[3])
        : "r"(a[0]), "r"(a[1]), "r"(a[2]), "r"(a[3]), "r"(b[0]), "r"(b[1]));
}

// ---------------- TF32-split GEMM: C[M,N] = A[M,K] @ B[K,N] + bias[N] ----
// 128x128 tile, BK=16, 256 threads (8 warps, warp tile 64x32).
// hi/lo TF32 split stored in smem (stride 136 -> conflict-free fragment LDS).
// Double buffered, one __syncthreads per K-step. M must be multiple of 128,
// K multiple of 16, N multiple of 4 (partial N tiles handled).
#define PADM 136
#define STG_A_HI 0
#define STG_A_LO (16*PADM)
#define STG_B_HI (2*16*PADM)
#define STG_B_LO (3*16*PADM)
#define STG_STRIDE (4*16*PADM)      // floats per stage
#define GEMM_SMEM_BYTES (2*STG_STRIDE*4)

__global__ __launch_bounds__(256, 1) void gemm_tf32_split(
    const float* __restrict__ A, const float* __restrict__ Bm,
    const float* __restrict__ bias, float* __restrict__ C,
    int M, int N, int K)
{
    extern __shared__ float sm[];
    const int tid  = threadIdx.x;
    const int bm   = blockIdx.y * 128;
    const int bn   = blockIdx.x * 128;
    const int warp = tid >> 5, lane = tid & 31;
    const int wm   = (warp >> 2) * 64;   // 0 or 64
    const int wn   = (warp & 3) * 32;    // 0,32,64,96
    const int gid  = lane >> 2;          // 0..7
    const int tig  = lane & 3;           // 0..3

    float acc[4][4][4];
    #pragma unroll
    for (int i = 0; i < 4; i++)
        #pragma unroll
        for (int j = 0; j < 4; j++)
            #pragma unroll
            for (int c = 0; c < 4; c++) acc[i][j][c] = 0.f;

    const int NT = K / 16;
    float4 ra[2], rb[2];

    // ---- G2R: load tile kt into registers ----
    auto g2r = [&](int kt) {
        int k0 = kt * 16;
        #pragma unroll
        for (int i = 0; i < 2; i++) {
            int idx = tid + i * 256;
            { // A: 128 rows x 16 k = 512 float4
                int row = idx >> 2, c4 = idx & 3;
                ra[i] = *(const float4*)&A[(size_t)(bm + row) * K + k0 + c4 * 4];
            }
            { // B: 16 k x 128 n = 512 float4
                int krow = idx >> 5, n4 = idx & 31;
                int col = bn + n4 * 4;
                if (col < N)
                    rb[i] = *(const float4*)&Bm[(size_t)(k0 + krow) * N + col];
                else
                    rb[i] = make_float4(0.f, 0.f, 0.f, 0.f);
            }
        }
    };

    // ---- R2S: split to tf32 hi/lo and store into stage s ----
    auto r2s = [&](int s) {
        float* Ah = sm + s * STG_STRIDE + STG_A_HI;
        float* Al = sm + s * STG_STRIDE + STG_A_LO;
        float* Bh = sm + s * STG_STRIDE + STG_B_HI;
        float* Bl = sm + s * STG_STRIDE + STG_B_LO;
        #pragma unroll
        for (int i = 0; i < 2; i++) {
            int idx = tid + i * 256;
            { // A transpose-store: As[k][m]
                int row = idx >> 2, c4 = idx & 3;
                float v[4] = {ra[i].x, ra[i].y, ra[i].z, ra[i].w};
                #pragma unroll
                for (int j = 0; j < 4; j++) {
                    int k = c4 * 4 + j;
                    uint32_t hb = f2tf32(v[j]);
                    float hf = __uint_as_float(hb);
                    uint32_t lb = f2tf32(v[j] - hf);
                    Ah[k * PADM + row] = hf;
                    Al[k * PADM + row] = __uint_as_float(lb);
                }
            }
            { // B straight store: Bs[k][n]
                int krow = idx >> 5, n4 = idx & 31;
                float v[4] = {rb[i].x, rb[i].y, rb[i].z, rb[i].w};
                float h[4], l[4];
                #pragma unroll
                for (int j = 0; j < 4; j++) {
                    uint32_t hb = f2tf32(v[j]);
                    h[j] = __uint_as_float(hb);
                    l[j] = __uint_as_float(f2tf32(v[j] - h[j]));
                }
                *(float4*)&Bh[krow * PADM + n4 * 4] = make_float4(h[0], h[1], h[2], h[3]);
                *(float4*)&Bl[krow * PADM + n4 * 4] = make_float4(l[0], l[1], l[2], l[3]);
            }
        }
    };

    // ---- compute one stage (2 x k8 steps) ----
    auto compute = [&](int s) {
        const float* Ah = sm + s * STG_STRIDE + STG_A_HI;
        const float* Al = sm + s * STG_STRIDE + STG_A_LO;
        const float* Bh = sm + s * STG_STRIDE + STG_B_HI;
        const float* Bl = sm + s * STG_STRIDE + STG_B_LO;
        #pragma unroll
        for (int k8 = 0; k8 < 16; k8 += 8) {
            uint32_t a_hi[4][4], a_lo[4][4], b_hi[4][2], b_lo[4][2];
            #pragma unroll
            for (int mt = 0; mt < 4; mt++) {
                int m = wm + mt * 16 + gid;
                int kA = (k8 + tig) * PADM;
                int kA4 = (k8 + tig + 4) * PADM;
                a_hi[mt][0] = __float_as_uint(Ah[kA  + m]);
                a_hi[mt][1] = __float_as_uint(Ah[kA  + m + 8]);
                a_hi[mt][2] = __float_as_uint(Ah[kA4 + m]);
                a_hi[mt][3] = __float_as_uint(Ah[kA4 + m + 8]);
                a_lo[mt][0] = __float_as_uint(Al[kA  + m]);
                a_lo[mt][1] = __float_as_uint(Al[kA  + m + 8]);
                a_lo[mt][2] = __float_as_uint(Al[kA4 + m]);
                a_lo[mt][3] = __float_as_uint(Al[kA4 + m + 8]);
            }
            #pragma unroll
            for (int nt = 0; nt < 4; nt++) {
                int n = wn + nt * 8 + gid;
                int kB = (k8 + tig) * PADM;
                int kB4 = (k8 + tig + 4) * PADM;
                b_hi[nt][0] = __float_as_uint(Bh[kB  + n]);
                b_hi[nt][1] = __float_as_uint(Bh[kB4 + n]);
                b_lo[nt][0] = __float_as_uint(Bl[kB  + n]);
                b_lo[nt][1] = __float_as_uint(Bl[kB4 + n]);
            }
            #pragma unroll
            for (int mt = 0; mt < 4; mt++)
                #pragma unroll
                for (int nt = 0; nt < 4; nt++) {
                    mma_tf32(acc[mt][nt], a_lo[mt], b_hi[nt]);
                    mma_tf32(acc[mt][nt], a_hi[mt], b_lo[nt]);
                    mma_tf32(acc[mt][nt], a_hi[mt], b_hi[nt]);
                }
        }
    };

    // ---- pipeline ----
    g2r(0);
    r2s(0);
    __syncthreads();
    for (int t = 0; t < NT; t++) {
        if (t + 1 < NT) g2r(t + 1);
        compute(t & 1);
        if (t + 1 < NT) {
            r2s((t + 1) & 1);
            __syncthreads();
        }
    }

    // ---- epilogue: bias add, fp32 store ----
    #pragma unroll
    for (int mt = 0; mt < 4; mt++) {
        #pragma unroll
        for (int nt = 0; nt < 4; nt++) {
            int row = bm + wm + mt * 16 + gid;
            int col = bn + wn + nt * 8 + tig * 2;
            if (col < N) {
                float b0 = bias[col], b1 = bias[col + 1];
                float2 v0 = make_float2(acc[mt][nt][0] + b0, acc[mt][nt][1] + b1);
                float2 v1 = make_float2(acc[mt][nt][2] + b0, acc[mt][nt][3] + b1);
                *(float2*)&C[(size_t)row * N + col] = v0;
                *(float2*)&C[(size_t)(row + 8) * N + col] = v1;
            }
        }
    }
}

// ---------------- NeoX RoPE (in place) ----------------
__global__ void rope_kernel(float* __restrict__ x, const int* __restrict__ pos,
                            int T, int H)
{
    int idx = blockIdx.x * blockDim.x + threadIdx.x;
    const int half = DD/2;              // 32
    int total = T * H * half;
    if (idx >= total) return;
    int j = idx & 31;
    int h = (idx >> 5) % H;
    int t = idx / (half * H);

    float inv = powf(THETA, -(float)j / 32.0f);
    float ang = (float)pos[t] * inv;
    float c, s;
    sincosf(ang, &s, &c);

    float* base = x + ((size_t)t * H + h) * DD;
    float x1 = base[j];
    float x2 = base[j + half];
    base[j]        = x1 * c - x2 * s;
    base[j + half] = x1 * s + x2 * c;
}

// ---------------- sliding-window GQA attention ----------------
#define KVPAD 65
#define SCPAD 132
#define SM_KS 0
#define SM_VS (129*KVPAD)
#define SM_QS (2*129*KVPAD)
#define SM_SC (2*129*KVPAD + GG*DD)
#define SM_FLOATS (2*129*KVPAD + GG*DD + GG*SCPAD)

__global__ __launch_bounds__(128) void attn_kernel(float* __restrict__ out)
{
    extern __shared__ float sm[];
    float* Ks = sm + SM_KS;   // [129][65]
    float* Vs = sm + SM_VS;   // [129][65]
    float* qs = sm + SM_QS;   // [8][64]
    float* sc = sm + SM_SC;   // [8][132]

    const int kh = blockIdx.x;
    const int i  = blockIdx.y;
    const int b  = blockIdx.z;
    const int t  = b * SS + i;
    const int tid = threadIdx.x;

    for (int idx = tid; idx < 129 * DD; idx += 128) {
        int w = idx >> 6, d = idx & 63;
        int p = i - WW + w;
        float kv = 0.f, vv = 0.f;
        if (p >= 0) {
            size_t off = ((size_t)(b * SS + p) * HKV + kh) * DD + d;
            kv = g_k[off];
            vv = g_v[off];
        }
        Ks[w * KVPAD + d] = kv;
        Vs[w * KVPAD + d] = vv;
    }
    for (int idx = tid; idx < GG * DD; idx += 128) {
        int g = idx >> 6, d = idx & 63;
        qs[idx] = g_q[((size_t)t * HQ + kh * GG + g) * DD + d];
    }
    __syncthreads();

    for (int idx = tid; idx < GG * 129; idx += 128) {
        int g = idx / 129, w = idx % 129;
        const float* qp = &qs[g * DD];
        const float* kp = &Ks[w * KVPAD];
        float s = 0.f;
        #pragma unroll 16
        for (int d = 0; d < DD; d++) s += qp[d] * kp[d];
        int p = i - WW + w;
        sc[g * SCPAD + w] = (p >= 0) ? s * SCALE : -1e30f;
    }
    __syncthreads();

    const int warp = tid >> 5, lane = tid & 31;
    for (int g = warp; g < GG; g += 4) {
        float m = -1e30f;
        for (int w = lane; w < 129; w += 32) m = fmaxf(m, sc[g * SCPAD + w]);
        #pragma unroll
        for (int o = 16; o; o >>= 1) m = fmaxf(m, __shfl_xor_sync(0xffffffffu, m, o));
        float sum = 0.f;
        for (int w = lane; w < 129; w += 32) {
            float e = __expf(sc[g * SCPAD + w] - m);
            sc[g * SCPAD + w] = e;
            sum += e;
        }
        #pragma unroll
        for (int o = 16; o; o >>= 1) sum += __shfl_xor_sync(0xffffffffu, sum, o);
        float inv = 1.f / sum;
        for (int w = lane; w < 129; w += 32) sc[g * SCPAD + w] *= inv;
    }
    __syncthreads();

    for (int idx = tid; idx < GG * DD; idx += 128) {
        int g = idx >> 6, d = idx & 63;
        const float* pr = &sc[g * SCPAD];
        const float* vp = &Vs[d];
        float o = 0.f;
        #pragma unroll 16
        for (int w = 0; w < 129; w++) o += pr[w] * vp[w * KVPAD];
        out[((size_t)t * HQ + kh * GG + g) * DD + d] = o;
    }
}

// ---------------- launch ----------------
extern "C" void kernel_launch(void* const* d_in, const int* in_sizes, int n_in,
                              void* d_out, int out_size)
{
    const float* hs = (const float*)d_in[0];
    const int*  pos = (const int*)  d_in[1];
    const float* Wq = (const float*)d_in[2];
    const float* bq = (const float*)d_in[3];
    const float* Wk = (const float*)d_in[4];
    const float* bk = (const float*)d_in[5];
    const float* Wv = (const float*)d_in[6];
    const float* bv = (const float*)d_in[7];
    const float* Wo = (const float*)d_in[8];
    const float* bo = (const float*)d_in[9];
    float* out = (float*)d_out;

    float *q, *k, *v, *att;
    cudaGetSymbolAddress((void**)&q,   g_q);
    cudaGetSymbolAddress((void**)&k,   g_k);
    cudaGetSymbolAddress((void**)&v,   g_v);
    cudaGetSymbolAddress((void**)&att, g_att);

    cudaFuncSetAttribute(gemm_tf32_split, cudaFuncAttributeMaxDynamicSharedMemorySize, GEMM_SMEM_BYTES);

    // QKV projections
    {
        dim3 gq((QSZ + 127) / 128, TT / 128);
        gemm_tf32_split<<<gq, 256, GEMM_SMEM_BYTES>>>(hs, Wq, bq, q, TT, QSZ, HID);
        dim3 gk((KVSZ + 127) / 128, TT / 128);
        gemm_tf32_split<<<gk, 256, GEMM_SMEM_BYTES>>>(hs, Wk, bk, k, TT, KVSZ, HID);
        gemm_tf32_split<<<gk, 256, GEMM_SMEM_BYTES>>>(hs, Wv, bv, v, TT, KVSZ, HID);
    }

    // RoPE on q and k
    {
        int tq = TT * HQ * (DD/2);
        rope_kernel<<<(tq + 255) / 256, 256>>>(q, pos, TT, HQ);
        int tk = TT * HKV * (DD/2);
        rope_kernel<<<(tk + 255) / 256, 256>>>(k, pos, TT, HKV);
    }

    // attention
    {
        size_t smem = SM_FLOATS * sizeof(float);
        cudaFuncSetAttribute(attn_kernel, cudaFuncAttributeMaxDynamicSharedMemorySize, (int)smem);
        dim3 ga(HKV, SS, BB);
        attn_kernel<<<ga, 128, smem>>>(att);
    }

    // output projection
    {
        dim3 go((HID + 127) / 128, TT / 128);
        gemm_tf32_split<<<go, 256, GEMM_SMEM_BYTES>>>(att, Wo, bo, out, TT, HID, QSZ);
    }
}

// round 4
// speedup vs baseline: 2.0239x; 1.3663x over previous
#include <cuda_runtime.h>
#include <cuda_fp16.h>
#include <cstdint>

// ---------------- problem constants ----------------
#define BB 2
#define SS 1024
#define TT (BB*SS)      // 2048 tokens
#define HID 2880
#define HQ 64
#define HKV 8
#define DD 64
#define GG (HQ/HKV)     // 8
#define WW 128
#define QSZ (HQ*DD)     // 4096
#define KVSZ (HKV*DD)   // 512
#define QKVSZ (QSZ + 2*KVSZ)  // 5120
#define SCALE 0.125f
#define THETA 150000.0f
#define WSCALE 64.0f
#define OSCALE (1.0f/64.0f)

// ---------------- scratch (no allocation allowed) ----------------
__device__ __half g_hs_hi[TT*HID];
__device__ __half g_hs_lo[TT*HID];
__device__ __half g_Wqkv_hi[QKVSZ*HID];   // [n][k] K-major, n in combined qkv order
__device__ __half g_Wqkv_lo[QKVSZ*HID];
__device__ float  g_bqkv[QKVSZ];
__device__ float  g_qkv[TT*QKVSZ];        // q | k | v per token
__device__ __half g_Wo_hi[HID*QSZ];       // [n=HID][k=QSZ]
__device__ __half g_Wo_lo[HID*QSZ];
__device__ __half g_att_hi[TT*QSZ];
__device__ __half g_att_lo[TT*QSZ];

// ---------------- low-level helpers ----------------
__device__ __forceinline__ uint32_t smem_u32(const void* p) {
    uint32_t a;
    asm("{ .reg .u64 t; cvta.to.shared.u64 t, %1; cvt.u32.u64 %0, t; }" : "=r"(a) : "l"(p));
    return a;
}

__device__ __forceinline__ void cp_async16(uint32_t dst, const void* src, bool valid) {
    int sz = valid ? 16 : 0;
    asm volatile("cp.async.cg.shared.global [%0], [%1], 16, %2;"
                 :: "r"(dst), "l"(src), "r"(sz));
}
#define CP_COMMIT asm volatile("cp.async.commit_group;")
template<int NN> __device__ __forceinline__ void cp_wait() {
    asm volatile("cp.async.wait_group %0;" :: "n"(NN));
}

__device__ __forceinline__ void ldsm_x4(uint32_t r[4], uint32_t addr) {
    asm volatile("ldmatrix.sync.aligned.m8n8.x4.shared.b16 {%0,%1,%2,%3}, [%4];"
        : "=r"(r[0]), "=r"(r[1]), "=r"(r[2]), "=r"(r[3]) : "r"(addr));
}

__device__ __forceinline__ void mma_f16(float c[4], const uint32_t a[4],
                                        uint32_t b0, uint32_t b1) {
    asm volatile(
        "mma.sync.aligned.m16n8k16.row.col.f32.f16.f16.f32 "
        "{%0,%1,%2,%3}, {%4,%5,%6,%7}, {%8,%9}, {%0,%1,%2,%3};"
        : "+f"(c[0]), "+f"(c[1]), "+f"(c[2]), "+f"(c[3])
        : "r"(a[0]), "r"(a[1]), "r"(a[2]), "r"(a[3]), "r"(b0), "r"(b1));
}

// ---------------- fp16-split GEMM ----------------
// C[M,N] = (A[M,K] @ BT[N,K]^T) * oscale + bias.  A/BT are fp16 hi/lo pairs.
// CTA tile 128x128, BK=32, 256 threads / 8 warps, warp tile 64x32.
// smem layout per stage: [Ah 8K | Al 8K | Bh 8K | Bl 8K].
// Within each region: ktile(2)*4096 + tile16(8)*512 + chunk'*16, chunk' = (h*16+r%16)^(4kt+2h).
#define BK 32
#define STG_BYTES 32768
#define GEMM_SMEM (2*STG_BYTES + 128)

__global__ __launch_bounds__(256, 2) void gemm_f16split(
    const __half* __restrict__ Ah, const __half* __restrict__ Al,
    const __half* __restrict__ Bh, const __half* __restrict__ Bl,
    const float* __restrict__ bias, float* __restrict__ C,
    int M, int N, int K, float oscale)
{
    extern __shared__ char raw[];
    const uint32_t base = (smem_u32(raw) + 127u) & ~127u;

    const int tid  = threadIdx.x;
    const int warp = tid >> 5, lane = tid & 31;
    const int bm = blockIdx.y * 128;
    const int bn = blockIdx.x * 128;
    const int wm = (warp >> 2) * 64;
    const int wn = (warp & 3) * 32;
    const int wmt = wm >> 4;
    const int wnt = wn >> 4;

    float acc[4][4][4];
    #pragma unroll
    for (int i = 0; i < 4; i++)
        #pragma unroll
        for (int j = 0; j < 4; j++)
            #pragma unroll
            for (int c = 0; c < 4; c++) acc[i][j][c] = 0.f;

    // per-lane swizzled ldmatrix offsets for ktile 0/1
    uint32_t lsw[2];
    {
        int h = lane >> 4;
        lsw[0] = (uint32_t)((lane ^ ((2 * h) & 7)) * 16);
        lsw[1] = (uint32_t)((lane ^ ((4 + 2 * h) & 7)) * 16);
    }

    const int NB = K / BK;

    auto issue = [&](int s, int k0) {
        uint32_t stg = base + (uint32_t)s * STG_BYTES;
        #pragma unroll
        for (int i = 0; i < 8; i++) {
            int region = i >> 1;            // 0 Ah, 1 Al, 2 Bh, 3 Bl
            int idx = tid + (i & 1) * 256;  // 0..511
            int hp = idx & 3;               // k-half' 0..3
            int r  = idx >> 2;              // row 0..127
            int kt = hp >> 1, hh = hp & 1;
            int cc = hh * 16 + (r & 15);
            int cs = cc ^ (hp * 2);         // = cc ^ (4kt+2h)
            uint32_t dst = stg + region * 8192 + kt * 4096 + (r >> 4) * 512 + cs * 16;
            const __half* sp;
            bool valid = true;
            if (region < 2) {
                sp = (region == 0 ? Ah : Al) + (size_t)(bm + r) * K + k0 + hp * 8;
            } else {
                int row = bn + r;
                valid = row < N;
                if (!valid) row = N - 1;
                sp = (region == 2 ? Bh : Bl) + (size_t)row * K + k0 + hp * 8;
            }
            cp_async16(dst, sp, valid);
        }
    };

    auto compute = [&](int s) {
        uint32_t stg = base + (uint32_t)s * STG_BYTES;
        #pragma unroll
        for (int kt = 0; kt < 2; kt++) {
            uint32_t sw = lsw[kt];
            uint32_t bfr_h[2][4], bfr_l[2][4];
            #pragma unroll
            for (int np = 0; np < 2; np++) {
                uint32_t baddr = stg + 16384 + kt * 4096 + (wnt + np) * 512 + sw;
                ldsm_x4(bfr_h[np], baddr);
                ldsm_x4(bfr_l[np], baddr + 8192);
            }
            #pragma unroll
            for (int mt = 0; mt < 4; mt++) {
                uint32_t aaddr = stg + kt * 4096 + (wmt + mt) * 512 + sw;
                uint32_t ah[4], al[4];
                ldsm_x4(ah, aaddr);
                ldsm_x4(al, aaddr + 8192);
                #pragma unroll
                for (int nt = 0; nt < 4; nt++) {
                    int np = nt >> 1, wq = nt & 1;
                    uint32_t bh0 = bfr_h[np][wq], bh1 = bfr_h[np][wq + 2];
                    uint32_t bl0 = bfr_l[np][wq], bl1 = bfr_l[np][wq + 2];
                    mma_f16(acc[mt][nt], ah, bh0, bh1);
                    mma_f16(acc[mt][nt], ah, bl0, bl1);
                    mma_f16(acc[mt][nt], al, bh0, bh1);
                }
            }
        }
    };

    issue(0, 0); CP_COMMIT;
    for (int b = 0; b < NB; b++) {
        if (b + 1 < NB) { issue((b + 1) & 1, (b + 1) * BK); CP_COMMIT; cp_wait<1>(); }
        else cp_wait<0>();
        __syncthreads();
        compute(b & 1);
        __syncthreads();
    }

    // epilogue
    const int l4 = lane >> 2, l2 = (lane & 3) * 2;
    #pragma unroll
    for (int mt = 0; mt < 4; mt++) {
        int row = bm + wm + mt * 16 + l4;
        #pragma unroll
        for (int nt = 0; nt < 4; nt++) {
            int col = bn + wn + nt * 8 + l2;
            if (col < N) {
                float b0 = bias[col], b1 = bias[col + 1];
                float2 v0 = make_float2(acc[mt][nt][0] * oscale + b0,
                                        acc[mt][nt][1] * oscale + b1);
                float2 v1 = make_float2(acc[mt][nt][2] * oscale + b0,
                                        acc[mt][nt][3] * oscale + b1);
                *(float2*)&C[(size_t)row * N + col] = v0;
                *(float2*)&C[(size_t)(row + 8) * N + col] = v1;
            }
        }
    }
}

// ---------------- fp16 split helpers ----------------
__device__ __forceinline__ void split_f16(float x, __half& h, __half& l) {
    h = __float2half_rn(x);
    l = __float2half_rn(x - __half2float(h));
}

// same-layout split: f32 -> f16 hi/lo
__global__ void convert_split(const float* __restrict__ src,
                              __half* __restrict__ hi, __half* __restrict__ lo, int n4)
{
    int i = blockIdx.x * blockDim.x + threadIdx.x;
    if (i >= n4) return;
    float4 v = *(const float4*)&src[(size_t)i * 4];
    __half h[4], l[4];
    split_f16(v.x, h[0], l[0]);
    split_f16(v.y, h[1], l[1]);
    split_f16(v.z, h[2], l[2]);
    split_f16(v.w, h[3], l[3]);
    *(uint2*)&hi[(size_t)i * 4] = *(uint2*)h;
    *(uint2*)&lo[(size_t)i * 4] = *(uint2*)l;
}

// transpose + scale + split: W[K][N] f32 -> out[(off+n)][K] f16 hi/lo
__global__ __launch_bounds__(256) void convert_transpose_split(
    const float* __restrict__ W, __half* __restrict__ hi, __half* __restrict__ lo,
    int K, int N, int out_off, float scale)
{
    __shared__ float tile[32][33];
    int tx = threadIdx.x, ty = threadIdx.y;
    int n0 = blockIdx.x * 32, k0 = blockIdx.y * 32;

    #pragma unroll
    for (int j = 0; j < 4; j++)
        tile[ty + j * 8][tx] = W[(size_t)(k0 + ty + j * 8) * N + n0 + tx];
    __syncthreads();
    #pragma unroll
    for (int j = 0; j < 4; j++) {
        int n = n0 + ty + j * 8;
        float v = tile[tx][ty + j * 8] * scale;
        __half h, l;
        split_f16(v, h, l);
        hi[(size_t)(out_off + n) * K + k0 + tx] = h;
        lo[(size_t)(out_off + n) * K + k0 + tx] = l;
    }
}

__global__ void concat_bias(const float* __restrict__ a, const float* __restrict__ b,
                            const float* __restrict__ c, float* __restrict__ out)
{
    int i = blockIdx.x * blockDim.x + threadIdx.x;
    if (i >= QKVSZ) return;
    float v;
    if (i < QSZ) v = a[i];
    else if (i < QSZ + KVSZ) v = b[i - QSZ];
    else v = c[i - QSZ - KVSZ];
    out[i] = v;
}

// ---------------- NeoX RoPE over combined qkv (q heads + k heads) ----------------
__global__ void rope_kernel(float* __restrict__ qkv, const int* __restrict__ pos)
{
    int idx = blockIdx.x * blockDim.x + threadIdx.x;
    const int half = DD / 2;
    const int HR = HQ + HKV;  // 72 rope heads
    int total = TT * HR * half;
    if (idx >= total) return;
    int j = idx & 31;
    int h = (idx >> 5) % HR;
    int t = idx / (half * HR);

    float inv = powf(THETA, -(float)j / 32.0f);
    float ang = (float)pos[t] * inv;
    float c, s;
    sincosf(ang, &s, &c);

    int colb = (h < HQ) ? h * DD : QSZ + (h - HQ) * DD;
    float* base = qkv + (size_t)t * QKVSZ + colb;
    float x1 = base[j];
    float x2 = base[j + half];
    base[j]        = x1 * c - x2 * s;
    base[j + half] = x1 * s + x2 * c;
}

// ---------------- sliding-window GQA attention ----------------
#define KVPAD 65
#define SCPAD 132
#define SM_KS 0
#define SM_VS (129*KVPAD)
#define SM_QS (2*129*KVPAD)
#define SM_SC (2*129*KVPAD + GG*DD)
#define SM_FLOATS (2*129*KVPAD + GG*DD + GG*SCPAD)

__global__ __launch_bounds__(128) void attn_kernel(
    __half* __restrict__ out_hi, __half* __restrict__ out_lo)
{
    extern __shared__ float sm[];
    float* Ks = sm + SM_KS;
    float* Vs = sm + SM_VS;
    float* qs = sm + SM_QS;
    float* sc = sm + SM_SC;

    const int kh = blockIdx.x;
    const int i  = blockIdx.y;
    const int b  = blockIdx.z;
    const int t  = b * SS + i;
    const int tid = threadIdx.x;

    for (int idx = tid; idx < 129 * DD; idx += 128) {
        int w = idx >> 6, d = idx & 63;
        int p = i - WW + w;
        float kv = 0.f, vv = 0.f;
        if (p >= 0) {
            size_t roff = (size_t)(b * SS + p) * QKVSZ;
            kv = g_qkv[roff + QSZ + kh * DD + d];
            vv = g_qkv[roff + QSZ + KVSZ + kh * DD + d];
        }
        Ks[w * KVPAD + d] = kv;
        Vs[w * KVPAD + d] = vv;
    }
    for (int idx = tid; idx < GG * DD; idx += 128) {
        int g = idx >> 6, d = idx & 63;
        qs[idx] = g_qkv[(size_t)t * QKVSZ + (kh * GG + g) * DD + d];
    }
    __syncthreads();

    for (int idx = tid; idx < GG * 129; idx += 128) {
        int g = idx / 129, w = idx % 129;
        const float* qp = &qs[g * DD];
        const float* kp = &Ks[w * KVPAD];
        float s = 0.f;
        #pragma unroll 16
        for (int d = 0; d < DD; d++) s += qp[d] * kp[d];
        int p = i - WW + w;
        sc[g * SCPAD + w] = (p >= 0) ? s * SCALE : -1e30f;
    }
    __syncthreads();

    const int warp = tid >> 5, lane = tid & 31;
    for (int g = warp; g < GG; g += 4) {
        float m = -1e30f;
        for (int w = lane; w < 129; w += 32) m = fmaxf(m, sc[g * SCPAD + w]);
        #pragma unroll
        for (int o = 16; o; o >>= 1) m = fmaxf(m, __shfl_xor_sync(0xffffffffu, m, o));
        float sum = 0.f;
        for (int w = lane; w < 129; w += 32) {
            float e = __expf(sc[g * SCPAD + w] - m);
            sc[g * SCPAD + w] = e;
            sum += e;
        }
        #pragma unroll
        for (int o = 16; o; o >>= 1) sum += __shfl_xor_sync(0xffffffffu, sum, o);
        float inv = 1.f / sum;
        for (int w = lane; w < 129; w += 32) sc[g * SCPAD + w] *= inv;
    }
    __syncthreads();

    for (int idx = tid; idx < GG * DD; idx += 128) {
        int g = idx >> 6, d = idx & 63;
        const float* pr = &sc[g * SCPAD];
        const float* vp = &Vs[d];
        float o = 0.f;
        #pragma unroll 16
        for (int w = 0; w < 129; w++) o += pr[w] * vp[w * KVPAD];
        size_t oidx = ((size_t)t * HQ + kh * GG + g) * DD + d;
        __half h, l;
        split_f16(o, h, l);
        out_hi[oidx] = h;
        out_lo[oidx] = l;
    }
}

// ---------------- launch ----------------
extern "C" void kernel_launch(void* const* d_in, const int* in_sizes, int n_in,
                              void* d_out, int out_size)
{
    const float* hs = (const float*)d_in[0];
    const int*  pos = (const int*)  d_in[1];
    const float* Wq = (const float*)d_in[2];
    const float* bq = (const float*)d_in[3];
    const float* Wk = (const float*)d_in[4];
    const float* bk = (const float*)d_in[5];
    const float* Wv = (const float*)d_in[6];
    const float* bv = (const float*)d_in[7];
    const float* Wo = (const float*)d_in[8];
    const float* bo = (const float*)d_in[9];
    float* out = (float*)d_out;

    __half *hs_hi, *hs_lo, *wqkv_hi, *wqkv_lo, *wo_hi, *wo_lo, *att_hi, *att_lo;
    float *bqkv, *qkv;
    cudaGetSymbolAddress((void**)&hs_hi,   g_hs_hi);
    cudaGetSymbolAddress((void**)&hs_lo,   g_hs_lo);
    cudaGetSymbolAddress((void**)&wqkv_hi, g_Wqkv_hi);
    cudaGetSymbolAddress((void**)&wqkv_lo, g_Wqkv_lo);
    cudaGetSymbolAddress((void**)&bqkv,    g_bqkv);
    cudaGetSymbolAddress((void**)&qkv,     g_qkv);
    cudaGetSymbolAddress((void**)&wo_hi,   g_Wo_hi);
    cudaGetSymbolAddress((void**)&wo_lo,   g_Wo_lo);
    cudaGetSymbolAddress((void**)&att_hi,  g_att_hi);
    cudaGetSymbolAddress((void**)&att_lo,  g_att_lo);

    cudaFuncSetAttribute(gemm_f16split, cudaFuncAttributeMaxDynamicSharedMemorySize, GEMM_SMEM);

    // operand conversion
    {
        int n4 = TT * HID / 4;
        convert_split<<<(n4 + 255) / 256, 256>>>(hs, hs_hi, hs_lo, n4);
        dim3 blk(32, 8);
        convert_transpose_split<<<dim3(QSZ / 32, HID / 32), blk>>>(Wq, wqkv_hi, wqkv_lo, HID, QSZ, 0, WSCALE);
        convert_transpose_split<<<dim3(KVSZ / 32, HID / 32), blk>>>(Wk, wqkv_hi, wqkv_lo, HID, KVSZ, QSZ, WSCALE);
        convert_transpose_split<<<dim3(KVSZ / 32, HID / 32), blk>>>(Wv, wqkv_hi, wqkv_lo, HID, KVSZ, QSZ + KVSZ, WSCALE);
        convert_transpose_split<<<dim3(HID / 32, QSZ / 32), blk>>>(Wo, wo_hi, wo_lo, QSZ, HID, 0, WSCALE);
        concat_bias<<<(QKVSZ + 255) / 256, 256>>>(bq, bk, bv, bqkv);
    }

    // fused QKV projection: [2048 x 2880] @ [2880 x 5120]
    gemm_f16split<<<dim3(QKVSZ / 128, TT / 128), 256, GEMM_SMEM>>>(
        hs_hi, hs_lo, wqkv_hi, wqkv_lo, bqkv, qkv, TT, QKVSZ, HID, OSCALE);

    // RoPE on q + k heads
    {
        int tot = TT * (HQ + HKV) * (DD / 2);
        rope_kernel<<<(tot + 255) / 256, 256>>>(qkv, pos);
    }

    // attention
    {
        size_t smem = SM_FLOATS * sizeof(float);
        cudaFuncSetAttribute(attn_kernel, cudaFuncAttributeMaxDynamicSharedMemorySize, (int)smem);
        dim3 ga(HKV, SS, BB);
        attn_kernel<<<ga, 128, smem>>>(att_hi, att_lo);
    }

    // output projection: [2048 x 4096] @ [4096 x 2880]
    gemm_f16split<<<dim3((HID + 127) / 128, TT / 128), 256, GEMM_SMEM>>>(
        att_hi, att_lo, wo_hi, wo_lo, bo, out, TT, HID, QSZ, OSCALE);
}

// round 5
// speedup vs baseline: 2.7518x; 1.3596x over previous
#include <cuda_runtime.h>
#include <cuda_fp16.h>
#include <cstdint>

// ---------------- problem constants ----------------
#define BB 2
#define SS 1024
#define TT (BB*SS)      // 2048 tokens
#define HID 2880
#define HQ 64
#define HKV 8
#define DD 64
#define GG (HQ/HKV)     // 8
#define WW 128
#define QSZ (HQ*DD)     // 4096
#define KVSZ (HKV*DD)   // 512
#define QKVSZ (QSZ + 2*KVSZ)  // 5120
#define SCALE 0.125f
#define THETA 150000.0f
#define WSCALE 64.0f
#define OSCALE (1.0f/64.0f)

// ---------------- scratch (no allocation allowed) ----------------
__device__ __half g_hs_hi[TT*HID];
__device__ __half g_Wqkv_hi[QKVSZ*HID];   // [n][k] K-major, combined q|k|v order
__device__ __half g_Wqkv_lo[QKVSZ*HID];
__device__ float  g_bqkv[QKVSZ];
__device__ float  g_qkv[TT*QKVSZ];        // q | k | v per token
__device__ __half g_Wo_hi[HID*QSZ];       // [n=HID][k=QSZ]
__device__ __half g_Wo_lo[HID*QSZ];
__device__ __half g_att_hi[TT*QSZ];

// ---------------- low-level helpers ----------------
__device__ __forceinline__ uint32_t smem_u32(const void* p) {
    uint32_t a;
    asm("{ .reg .u64 t; cvta.to.shared.u64 t, %1; cvt.u32.u64 %0, t; }" : "=r"(a) : "l"(p));
    return a;
}

__device__ __forceinline__ void cp_async16(uint32_t dst, const void* src, bool valid) {
    int sz = valid ? 16 : 0;
    asm volatile("cp.async.cg.shared.global [%0], [%1], 16, %2;"
                 :: "r"(dst), "l"(src), "r"(sz));
}
#define CP_COMMIT asm volatile("cp.async.commit_group;")
template<int NN> __device__ __forceinline__ void cp_wait() {
    asm volatile("cp.async.wait_group %0;" :: "n"(NN));
}

__device__ __forceinline__ void ldsm_x4(uint32_t r[4], uint32_t addr) {
    asm volatile("ldmatrix.sync.aligned.m8n8.x4.shared.b16 {%0,%1,%2,%3}, [%4];"
        : "=r"(r[0]), "=r"(r[1]), "=r"(r[2]), "=r"(r[3]) : "r"(addr));
}

__device__ __forceinline__ void mma_f16(float c[4], const uint32_t a[4],
                                        uint32_t b0, uint32_t b1) {
    asm volatile(
        "mma.sync.aligned.m16n8k16.row.col.f32.f16.f16.f32 "
        "{%0,%1,%2,%3}, {%4,%5,%6,%7}, {%8,%9}, {%0,%1,%2,%3};"
        : "+f"(c[0]), "+f"(c[1]), "+f"(c[2]), "+f"(c[3])
        : "r"(a[0]), "r"(a[1]), "r"(a[2]), "r"(a[3]), "r"(b0), "r"(b1));
}

// ---------------- fp16 2-pass split GEMM ----------------
// C[M,N] = (Ah[M,K] @ (BTh+BTl)[N,K]^T) * oscale + bias.
// CTA tile 128x128, BK=32, 256 threads / 8 warps, warp tile 64x32.
// Per stage (24KB): [Ah 8K | Bh 8K | Bl 8K]. 3 stages, 1 sync per K-iter.
// Region layout: ktile(2)*4096 + tile16(8)*512 + chunk'*16, chunk' = (h*16+r%16)^(4kt+2h).
#define BK 32
#define STG_BYTES 24576
#define GEMM_SMEM (3*STG_BYTES + 128)

__global__ __launch_bounds__(256, 2) void gemm_f16split2(
    const __half* __restrict__ Ah,
    const __half* __restrict__ Bh, const __half* __restrict__ Bl,
    const float* __restrict__ bias, float* __restrict__ C,
    int M, int N, int K, float oscale)
{
    extern __shared__ char raw[];
    const uint32_t base = (smem_u32(raw) + 127u) & ~127u;

    const int tid  = threadIdx.x;
    const int warp = tid >> 5, lane = tid & 31;
    const int bm = blockIdx.y * 128;
    const int bn = blockIdx.x * 128;
    const int wm = (warp >> 2) * 64;
    const int wn = (warp & 3) * 32;
    const int wmt = wm >> 4;
    const int wnt = wn >> 4;

    float acc[4][4][4];
    #pragma unroll
    for (int i = 0; i < 4; i++)
        #pragma unroll
        for (int j = 0; j < 4; j++)
            #pragma unroll
            for (int c = 0; c < 4; c++) acc[i][j][c] = 0.f;

    // per-lane swizzled ldmatrix offsets for ktile 0/1
    uint32_t lsw[2];
    {
        int h = lane >> 4;
        lsw[0] = (uint32_t)((lane ^ ((2 * h) & 7)) * 16);
        lsw[1] = (uint32_t)((lane ^ ((4 + 2 * h) & 7)) * 16);
    }

    const int NB = K / BK;

    auto issue = [&](int s, int k0) {
        uint32_t stg = base + (uint32_t)s * STG_BYTES;
        #pragma unroll
        for (int i = 0; i < 6; i++) {
            int region = i >> 1;            // 0 Ah, 1 Bh, 2 Bl
            int idx = tid + (i & 1) * 256;  // 0..511
            int hp = idx & 3;               // k-half 0..3
            int r  = idx >> 2;              // row 0..127
            int kt = hp >> 1, hh = hp & 1;
            int cc = hh * 16 + (r & 15);
            int cs = cc ^ (hp * 2);         // = cc ^ (4kt+2h)
            uint32_t dst = stg + region * 8192 + kt * 4096 + (r >> 4) * 512 + cs * 16;
            const __half* sp;
            bool valid = true;
            if (region == 0) {
                sp = Ah + (size_t)(bm + r) * K + k0 + hp * 8;
            } else {
                int row = bn + r;
                valid = row < N;
                if (!valid) row = N - 1;
                sp = (region == 1 ? Bh : Bl) + (size_t)row * K + k0 + hp * 8;
            }
            cp_async16(dst, sp, valid);
        }
    };

    auto compute = [&](int s) {
        uint32_t stg = base + (uint32_t)s * STG_BYTES;
        #pragma unroll
        for (int kt = 0; kt < 2; kt++) {
            uint32_t sw = lsw[kt];
            uint32_t bfr_h[2][4], bfr_l[2][4];
            #pragma unroll
            for (int np = 0; np < 2; np++) {
                uint32_t baddr = stg + 8192 + kt * 4096 + (wnt + np) * 512 + sw;
                ldsm_x4(bfr_h[np], baddr);
                ldsm_x4(bfr_l[np], baddr + 8192);
            }
            #pragma unroll
            for (int mt = 0; mt < 4; mt++) {
                uint32_t aaddr = stg + kt * 4096 + (wmt + mt) * 512 + sw;
                uint32_t ah[4];
                ldsm_x4(ah, aaddr);
                #pragma unroll
                for (int nt = 0; nt < 4; nt++) {
                    int np = nt >> 1, wq = nt & 1;
                    mma_f16(acc[mt][nt], ah, bfr_h[np][wq], bfr_h[np][wq + 2]);
                    mma_f16(acc[mt][nt], ah, bfr_l[np][wq], bfr_l[np][wq + 2]);
                }
            }
        }
    };

    issue(0, 0); CP_COMMIT;
    issue(1, BK); CP_COMMIT;
    for (int b = 0; b < NB; b++) {
        if (b + 1 < NB) cp_wait<1>(); else cp_wait<0>();
        __syncthreads();
        compute(b % 3);
        if (b + 2 < NB) { issue((b + 2) % 3, (b + 2) * BK); CP_COMMIT; }
    }

    // epilogue
    const int l4 = lane >> 2, l2 = (lane & 3) * 2;
    #pragma unroll
    for (int mt = 0; mt < 4; mt++) {
        int row = bm + wm + mt * 16 + l4;
        #pragma unroll
        for (int nt = 0; nt < 4; nt++) {
            int col = bn + wn + nt * 8 + l2;
            if (col < N) {
                float b0 = bias[col], b1 = bias[col + 1];
                float2 v0 = make_float2(acc[mt][nt][0] * oscale + b0,
                                        acc[mt][nt][1] * oscale + b1);
                float2 v1 = make_float2(acc[mt][nt][2] * oscale + b0,
                                        acc[mt][nt][3] * oscale + b1);
                *(float2*)&C[(size_t)row * N + col] = v0;
                *(float2*)&C[(size_t)(row + 8) * N + col] = v1;
            }
        }
    }
}

// ---------------- conversion kernels ----------------
__device__ __forceinline__ void split_f16(float x, __half& h, __half& l) {
    h = __float2half_rn(x);
    l = __float2half_rn(x - __half2float(h));
}

// f32 -> f16 hi only (same layout)
__global__ void convert_hi(const float* __restrict__ src,
                           __half* __restrict__ hi, int n4)
{
    int i = blockIdx.x * blockDim.x + threadIdx.x;
    if (i >= n4) return;
    float4 v = *(const float4*)&src[(size_t)i * 4];
    __half h[4];
    h[0] = __float2half_rn(v.x);
    h[1] = __float2half_rn(v.y);
    h[2] = __float2half_rn(v.z);
    h[3] = __float2half_rn(v.w);
    *(uint2*)&hi[(size_t)i * 4] = *(uint2*)h;
}

// shared transpose+scale+split body
__device__ __forceinline__ void cts_body(
    const float* __restrict__ W, __half* __restrict__ hi, __half* __restrict__ lo,
    int K, int N, int out_off, float scale, int bx, int by,
    float tile[32][33])
{
    int tx = threadIdx.x, ty = threadIdx.y;
    int n0 = bx * 32, k0 = by * 32;
    #pragma unroll
    for (int j = 0; j < 4; j++)
        tile[ty + j * 8][tx] = W[(size_t)(k0 + ty + j * 8) * N + n0 + tx];
    __syncthreads();
    #pragma unroll
    for (int j = 0; j < 4; j++) {
        int n = n0 + ty + j * 8;
        float v = tile[tx][ty + j * 8] * scale;
        __half h, l;
        split_f16(v, h, l);
        hi[(size_t)(out_off + n) * K + k0 + tx] = h;
        lo[(size_t)(out_off + n) * K + k0 + tx] = l;
    }
}

// fused Wq|Wk|Wv transpose+split into combined buffer. grid: (160, 90)
__global__ __launch_bounds__(256) void cts_qkv(
    const float* __restrict__ Wq, const float* __restrict__ Wk,
    const float* __restrict__ Wv,
    __half* __restrict__ hi, __half* __restrict__ lo)
{
    __shared__ float tile[32][33];
    int bx = blockIdx.x;
    const float* W; int N, off;
    if (bx < QSZ / 32) { W = Wq; N = QSZ; off = 0; }
    else if (bx < (QSZ + KVSZ) / 32) { W = Wk; N = KVSZ; off = QSZ; bx -= QSZ / 32; }
    else { W = Wv; N = KVSZ; off = QSZ + KVSZ; bx -= (QSZ + KVSZ) / 32; }
    cts_body(W, hi, lo, HID, N, off, WSCALE, bx, blockIdx.y, tile);
}

// Wo transpose+split. grid: (HID/32, QSZ/32)
__global__ __launch_bounds__(256) void cts_wo(
    const float* __restrict__ Wo, __half* __restrict__ hi, __half* __restrict__ lo)
{
    __shared__ float tile[32][33];
    cts_body(Wo, hi, lo, QSZ, HID, 0, WSCALE, blockIdx.x, blockIdx.y, tile);
}

__global__ void concat_bias(const float* __restrict__ a, const float* __restrict__ b,
                            const float* __restrict__ c, float* __restrict__ out)
{
    int i = blockIdx.x * blockDim.x + threadIdx.x;
    if (i >= QKVSZ) return;
    float v;
    if (i < QSZ) v = a[i];
    else if (i < QSZ + KVSZ) v = b[i - QSZ];
    else v = c[i - QSZ - KVSZ];
    out[i] = v;
}

// ---------------- NeoX RoPE over combined qkv (q heads + k heads) ----------------
__global__ void rope_kernel(float* __restrict__ qkv, const int* __restrict__ pos)
{
    int idx = blockIdx.x * blockDim.x + threadIdx.x;
    const int half = DD / 2;
    const int HR = HQ + HKV;  // 72 rope heads
    int total = TT * HR * half;
    if (idx >= total) return;
    int j = idx & 31;
    int h = (idx >> 5) % HR;
    int t = idx / (half * HR);

    float inv = powf(THETA, -(float)j / 32.0f);
    float ang = (float)pos[t] * inv;
    float c, s;
    sincosf(ang, &s, &c);

    int colb = (h < HQ) ? h * DD : QSZ + (h - HQ) * DD;
    float* base = qkv + (size_t)t * QKVSZ + colb;
    float x1 = base[j];
    float x2 = base[j + half];
    base[j]        = x1 * c - x2 * s;
    base[j + half] = x1 * s + x2 * c;
}

// ---------------- sliding-window GQA attention ----------------
#define KVPAD 65
#define SCPAD 132
#define SM_KS 0
#define SM_VS (129*KVPAD)
#define SM_QS (2*129*KVPAD)
#define SM_SC (2*129*KVPAD + GG*DD)
#define SM_FLOATS (2*129*KVPAD + GG*DD + GG*SCPAD)

__global__ __launch_bounds__(128) void attn_kernel(__half* __restrict__ out_hi)
{
    extern __shared__ float sm[];
    float* Ks = sm + SM_KS;
    float* Vs = sm + SM_VS;
    float* qs = sm + SM_QS;
    float* sc = sm + SM_SC;

    const int kh = blockIdx.x;
    const int i  = blockIdx.y;
    const int b  = blockIdx.z;
    const int t  = b * SS + i;
    const int tid = threadIdx.x;

    for (int idx = tid; idx < 129 * DD; idx += 128) {
        int w = idx >> 6, d = idx & 63;
        int p = i - WW + w;
        float kv = 0.f, vv = 0.f;
        if (p >= 0) {
            size_t roff = (size_t)(b * SS + p) * QKVSZ;
            kv = g_qkv[roff + QSZ + kh * DD + d];
            vv = g_qkv[roff + QSZ + KVSZ + kh * DD + d];
        }
        Ks[w * KVPAD + d] = kv;
        Vs[w * KVPAD + d] = vv;
    }
    for (int idx = tid; idx < GG * DD; idx += 128) {
        int g = idx >> 6, d = idx & 63;
        qs[idx] = g_qkv[(size_t)t * QKVSZ + (kh * GG + g) * DD + d];
    }
    __syncthreads();

    for (int idx = tid; idx < GG * 129; idx += 128) {
        int g = idx / 129, w = idx % 129;
        const float* qp = &qs[g * DD];
        const float* kp = &Ks[w * KVPAD];
        float s = 0.f;
        #pragma unroll 16
        for (int d = 0; d < DD; d++) s += qp[d] * kp[d];
        int p = i - WW + w;
        sc[g * SCPAD + w] = (p >= 0) ? s * SCALE : -1e30f;
    }
    __syncthreads();

    const int warp = tid >> 5, lane = tid & 31;
    for (int g = warp; g < GG; g += 4) {
        float m = -1e30f;
        for (int w = lane; w < 129; w += 32) m = fmaxf(m, sc[g * SCPAD + w]);
        #pragma unroll
        for (int o = 16; o; o >>= 1) m = fmaxf(m, __shfl_xor_sync(0xffffffffu, m, o));
        float sum = 0.f;
        for (int w = lane; w < 129; w += 32) {
            float e = __expf(sc[g * SCPAD + w] - m);
            sc[g * SCPAD + w] = e;
            sum += e;
        }
        #pragma unroll
        for (int o = 16; o; o >>= 1) sum += __shfl_xor_sync(0xffffffffu, sum, o);
        float inv = 1.f / sum;
        for (int w = lane; w < 129; w += 32) sc[g * SCPAD + w] *= inv;
    }
    __syncthreads();

    for (int idx = tid; idx < GG * DD; idx += 128) {
        int g = idx >> 6, d = idx & 63;
        const float* pr = &sc[g * SCPAD];
        const float* vp = &Vs[d];
        float o = 0.f;
        #pragma unroll 16
        for (int w = 0; w < 129; w++) o += pr[w] * vp[w * KVPAD];
        size_t oidx = ((size_t)t * HQ + kh * GG + g) * DD + d;
        out_hi[oidx] = __float2half_rn(o);
    }
}

// ---------------- launch ----------------
extern "C" void kernel_launch(void* const* d_in, const int* in_sizes, int n_in,
                              void* d_out, int out_size)
{
    const float* hs = (const float*)d_in[0];
    const int*  pos = (const int*)  d_in[1];
    const float* Wq = (const float*)d_in[2];
    const float* bq = (const float*)d_in[3];
    const float* Wk = (const float*)d_in[4];
    const float* bk = (const float*)d_in[5];
    const float* Wv = (const float*)d_in[6];
    const float* bv = (const float*)d_in[7];
    const float* Wo = (const float*)d_in[8];
    const float* bo = (const float*)d_in[9];
    float* out = (float*)d_out;

    __half *hs_hi, *wqkv_hi, *wqkv_lo, *wo_hi, *wo_lo, *att_hi;
    float *bqkv, *qkv;
    cudaGetSymbolAddress((void**)&hs_hi,   g_hs_hi);
    cudaGetSymbolAddress((void**)&wqkv_hi, g_Wqkv_hi);
    cudaGetSymbolAddress((void**)&wqkv_lo, g_Wqkv_lo);
    cudaGetSymbolAddress((void**)&bqkv,    g_bqkv);
    cudaGetSymbolAddress((void**)&qkv,     g_qkv);
    cudaGetSymbolAddress((void**)&wo_hi,   g_Wo_hi);
    cudaGetSymbolAddress((void**)&wo_lo,   g_Wo_lo);
    cudaGetSymbolAddress((void**)&att_hi,  g_att_hi);

    cudaFuncSetAttribute(gemm_f16split2, cudaFuncAttributeMaxDynamicSharedMemorySize, GEMM_SMEM);

    // (1) combined bias
    concat_bias<<<(QKVSZ + 255) / 256, 256>>>(bq, bk, bv, bqkv);
    // (2) hidden_states -> fp16 hi
    {
        int n4 = TT * HID / 4;
        convert_hi<<<(n4 + 255) / 256, 256>>>(hs, hs_hi, n4);
    }
    // (3) fused QKV weight transpose+split
    {
        dim3 blk(32, 8);
        cts_qkv<<<dim3(QKVSZ / 32, HID / 32), blk>>>(Wq, Wk, Wv, wqkv_hi, wqkv_lo);
        // (4) Wo transpose+split
        cts_wo<<<dim3(HID / 32, QSZ / 32), blk>>>(Wo, wo_hi, wo_lo);
    }
    // (5) fused QKV projection: [2048 x 2880] @ [2880 x 5120]   <-- profiled slot
    gemm_f16split2<<<dim3(QKVSZ / 128, TT / 128), 256, GEMM_SMEM>>>(
        hs_hi, wqkv_hi, wqkv_lo, bqkv, qkv, TT, QKVSZ, HID, OSCALE);
    // (6) RoPE on q + k heads
    {
        int tot = TT * (HQ + HKV) * (DD / 2);
        rope_kernel<<<(tot + 255) / 256, 256>>>(qkv, pos);
    }
    // (7) attention
    {
        size_t smem = SM_FLOATS * sizeof(float);
        cudaFuncSetAttribute(attn_kernel, cudaFuncAttributeMaxDynamicSharedMemorySize, (int)smem);
        dim3 ga(HKV, SS, BB);
        attn_kernel<<<ga, 128, smem>>>(att_hi);
    }
    // (8) output projection: [2048 x 4096] @ [4096 x 2880]
    gemm_f16split2<<<dim3((HID + 127) / 128, TT / 128), 256, GEMM_SMEM>>>(
        att_hi, wo_hi, wo_lo, bo, out, TT, HID, QSZ, OSCALE);
}

// round 6
// speedup vs baseline: 3.7104x; 1.3484x over previous
#include <cuda_runtime.h>
#include <cuda_fp16.h>
#include <cstdint>

// ---------------- problem constants ----------------
#define BB 2
#define SS 1024
#define TT (BB*SS)      // 2048 tokens
#define HID 2880
#define HQ 64
#define HKV 8
#define DD 64
#define GG (HQ/HKV)     // 8
#define WW 128
#define QSZ (HQ*DD)     // 4096
#define KVSZ (HKV*DD)   // 512
#define QKVSZ (QSZ + 2*KVSZ)  // 5120
#define SCALE 0.125f
#define THETA 150000.0f
#define WSCALE 64.0f
#define OSCALE (1.0f/64.0f)

// ---------------- scratch (no allocation allowed) ----------------
__device__ __half g_hs_hi[TT*HID];
__device__ __half g_Wqkv_hi[QKVSZ*HID];   // [n][k] K-major, combined q|k|v order
__device__ __half g_Wqkv_lo[QKVSZ*HID];
__device__ float  g_bqkv[QKVSZ];
__device__ float  g_qkv[TT*QKVSZ];        // q | k | v per token
__device__ __half g_Wo_hi[HID*QSZ];       // [n=HID][k=QSZ]
__device__ __half g_Wo_lo[HID*QSZ];
__device__ __half g_att_hi[TT*QSZ];

// ---------------- low-level helpers ----------------
__device__ __forceinline__ uint32_t smem_u32(const void* p) {
    uint32_t a;
    asm("{ .reg .u64 t; cvta.to.shared.u64 t, %1; cvt.u32.u64 %0, t; }" : "=r"(a) : "l"(p));
    return a;
}

__device__ __forceinline__ void cp_async16(uint32_t dst, const void* src, bool valid) {
    int sz = valid ? 16 : 0;
    asm volatile("cp.async.cg.shared.global [%0], [%1], 16, %2;"
                 :: "r"(dst), "l"(src), "r"(sz));
}
#define CP_COMMIT asm volatile("cp.async.commit_group;")
template<int NN> __device__ __forceinline__ void cp_wait() {
    asm volatile("cp.async.wait_group %0;" :: "n"(NN));
}

__device__ __forceinline__ void ldsm_x4(uint32_t r[4], uint32_t addr) {
    asm volatile("ldmatrix.sync.aligned.m8n8.x4.shared.b16 {%0,%1,%2,%3}, [%4];"
        : "=r"(r[0]), "=r"(r[1]), "=r"(r[2]), "=r"(r[3]) : "r"(addr));
}

__device__ __forceinline__ void mma_f16(float c[4], const uint32_t a[4],
                                        uint32_t b0, uint32_t b1) {
    asm volatile(
        "mma.sync.aligned.m16n8k16.row.col.f32.f16.f16.f32 "
        "{%0,%1,%2,%3}, {%4,%5,%6,%7}, {%8,%9}, {%0,%1,%2,%3};"
        : "+f"(c[0]), "+f"(c[1]), "+f"(c[2]), "+f"(c[3])
        : "r"(a[0]), "r"(a[1]), "r"(a[2]), "r"(a[3]), "r"(b0), "r"(b1));
}

// ---------------- fp16 2-pass split GEMM (unchanged from R5) ----------------
#define BK 32
#define STG_BYTES 24576
#define GEMM_SMEM (3*STG_BYTES + 128)

__global__ __launch_bounds__(256, 2) void gemm_f16split2(
    const __half* __restrict__ Ah,
    const __half* __restrict__ Bh, const __half* __restrict__ Bl,
    const float* __restrict__ bias, float* __restrict__ C,
    int M, int N, int K, float oscale)
{
    extern __shared__ char raw[];
    const uint32_t base = (smem_u32(raw) + 127u) & ~127u;

    const int tid  = threadIdx.x;
    const int warp = tid >> 5, lane = tid & 31;
    const int bm = blockIdx.y * 128;
    const int bn = blockIdx.x * 128;
    const int wm = (warp >> 2) * 64;
    const int wn = (warp & 3) * 32;
    const int wmt = wm >> 4;
    const int wnt = wn >> 4;

    float acc[4][4][4];
    #pragma unroll
    for (int i = 0; i < 4; i++)
        #pragma unroll
        for (int j = 0; j < 4; j++)
            #pragma unroll
            for (int c = 0; c < 4; c++) acc[i][j][c] = 0.f;

    uint32_t lsw[2];
    {
        int h = lane >> 4;
        lsw[0] = (uint32_t)((lane ^ ((2 * h) & 7)) * 16);
        lsw[1] = (uint32_t)((lane ^ ((4 + 2 * h) & 7)) * 16);
    }

    const int NB = K / BK;

    auto issue = [&](int s, int k0) {
        uint32_t stg = base + (uint32_t)s * STG_BYTES;
        #pragma unroll
        for (int i = 0; i < 6; i++) {
            int region = i >> 1;
            int idx = tid + (i & 1) * 256;
            int hp = idx & 3;
            int r  = idx >> 2;
            int kt = hp >> 1, hh = hp & 1;
            int cc = hh * 16 + (r & 15);
            int cs = cc ^ (hp * 2);
            uint32_t dst = stg + region * 8192 + kt * 4096 + (r >> 4) * 512 + cs * 16;
            const __half* sp;
            bool valid = true;
            if (region == 0) {
                sp = Ah + (size_t)(bm + r) * K + k0 + hp * 8;
            } else {
                int row = bn + r;
                valid = row < N;
                if (!valid) row = N - 1;
                sp = (region == 1 ? Bh : Bl) + (size_t)row * K + k0 + hp * 8;
            }
            cp_async16(dst, sp, valid);
        }
    };

    auto compute = [&](int s) {
        uint32_t stg = base + (uint32_t)s * STG_BYTES;
        #pragma unroll
        for (int kt = 0; kt < 2; kt++) {
            uint32_t sw = lsw[kt];
            uint32_t bfr_h[2][4], bfr_l[2][4];
            #pragma unroll
            for (int np = 0; np < 2; np++) {
                uint32_t baddr = stg + 8192 + kt * 4096 + (wnt + np) * 512 + sw;
                ldsm_x4(bfr_h[np], baddr);
                ldsm_x4(bfr_l[np], baddr + 8192);
            }
            #pragma unroll
            for (int mt = 0; mt < 4; mt++) {
                uint32_t aaddr = stg + kt * 4096 + (wmt + mt) * 512 + sw;
                uint32_t ah[4];
                ldsm_x4(ah, aaddr);
                #pragma unroll
                for (int nt = 0; nt < 4; nt++) {
                    int np = nt >> 1, wq = nt & 1;
                    mma_f16(acc[mt][nt], ah, bfr_h[np][wq], bfr_h[np][wq + 2]);
                    mma_f16(acc[mt][nt], ah, bfr_l[np][wq], bfr_l[np][wq + 2]);
                }
            }
        }
    };

    issue(0, 0); CP_COMMIT;
    issue(1, BK); CP_COMMIT;
    for (int b = 0; b < NB; b++) {
        if (b + 1 < NB) cp_wait<1>(); else cp_wait<0>();
        __syncthreads();
        compute(b % 3);
        if (b + 2 < NB) { issue((b + 2) % 3, (b + 2) * BK); CP_COMMIT; }
    }

    const int l4 = lane >> 2, l2 = (lane & 3) * 2;
    #pragma unroll
    for (int mt = 0; mt < 4; mt++) {
        int row = bm + wm + mt * 16 + l4;
        #pragma unroll
        for (int nt = 0; nt < 4; nt++) {
            int col = bn + wn + nt * 8 + l2;
            if (col < N) {
                float b0 = bias[col], b1 = bias[col + 1];
                float2 v0 = make_float2(acc[mt][nt][0] * oscale + b0,
                                        acc[mt][nt][1] * oscale + b1);
                float2 v1 = make_float2(acc[mt][nt][2] * oscale + b0,
                                        acc[mt][nt][3] * oscale + b1);
                *(float2*)&C[(size_t)row * N + col] = v0;
                *(float2*)&C[(size_t)(row + 8) * N + col] = v1;
            }
        }
    }
}

// ---------------- conversion kernels ----------------
__device__ __forceinline__ void split_f16(float x, __half& h, __half& l) {
    h = __float2half_rn(x);
    l = __float2half_rn(x - __half2float(h));
}

__global__ void convert_hi(const float* __restrict__ src,
                           __half* __restrict__ hi, int n4)
{
    int i = blockIdx.x * blockDim.x + threadIdx.x;
    if (i >= n4) return;
    float4 v = *(const float4*)&src[(size_t)i * 4];
    __half h[4];
    h[0] = __float2half_rn(v.x);
    h[1] = __float2half_rn(v.y);
    h[2] = __float2half_rn(v.z);
    h[3] = __float2half_rn(v.w);
    *(uint2*)&hi[(size_t)i * 4] = *(uint2*)h;
}

__device__ __forceinline__ void cts_body(
    const float* __restrict__ W, __half* __restrict__ hi, __half* __restrict__ lo,
    int K, int N, int out_off, float scale, int bx, int by,
    float tile[32][33])
{
    int tx = threadIdx.x, ty = threadIdx.y;
    int n0 = bx * 32, k0 = by * 32;
    #pragma unroll
    for (int j = 0; j < 4; j++)
        tile[ty + j * 8][tx] = W[(size_t)(k0 + ty + j * 8) * N + n0 + tx];
    __syncthreads();
    #pragma unroll
    for (int j = 0; j < 4; j++) {
        int n = n0 + ty + j * 8;
        float v = tile[tx][ty + j * 8] * scale;
        __half h, l;
        split_f16(v, h, l);
        hi[(size_t)(out_off + n) * K + k0 + tx] = h;
        lo[(size_t)(out_off + n) * K + k0 + tx] = l;
    }
}

__global__ __launch_bounds__(256) void cts_qkv(
    const float* __restrict__ Wq, const float* __restrict__ Wk,
    const float* __restrict__ Wv,
    __half* __restrict__ hi, __half* __restrict__ lo)
{
    __shared__ float tile[32][33];
    int bx = blockIdx.x;
    const float* W; int N, off;
    if (bx < QSZ / 32) { W = Wq; N = QSZ; off = 0; }
    else if (bx < (QSZ + KVSZ) / 32) { W = Wk; N = KVSZ; off = QSZ; bx -= QSZ / 32; }
    else { W = Wv; N = KVSZ; off = QSZ + KVSZ; bx -= (QSZ + KVSZ) / 32; }
    cts_body(W, hi, lo, HID, N, off, WSCALE, bx, blockIdx.y, tile);
}

__global__ __launch_bounds__(256) void cts_wo(
    const float* __restrict__ Wo, __half* __restrict__ hi, __half* __restrict__ lo)
{
    __shared__ float tile[32][33];
    cts_body(Wo, hi, lo, QSZ, HID, 0, WSCALE, blockIdx.x, blockIdx.y, tile);
}

__global__ void concat_bias(const float* __restrict__ a, const float* __restrict__ b,
                            const float* __restrict__ c, float* __restrict__ out)
{
    int i = blockIdx.x * blockDim.x + threadIdx.x;
    if (i >= QKVSZ) return;
    float v;
    if (i < QSZ) v = a[i];
    else if (i < QSZ + KVSZ) v = b[i - QSZ];
    else v = c[i - QSZ - KVSZ];
    out[i] = v;
}

// ---------------- NeoX RoPE over combined qkv (q heads + k heads) ----------------
__global__ void rope_kernel(float* __restrict__ qkv, const int* __restrict__ pos)
{
    int idx = blockIdx.x * blockDim.x + threadIdx.x;
    const int half = DD / 2;
    const int HR = HQ + HKV;  // 72 rope heads
    int total = TT * HR * half;
    if (idx >= total) return;
    int j = idx & 31;
    int h = (idx >> 5) % HR;
    int t = idx / (half * HR);

    float inv = powf(THETA, -(float)j / 32.0f);
    float ang = (float)pos[t] * inv;
    float c, s;
    sincosf(ang, &s, &c);

    int colb = (h < HQ) ? h * DD : QSZ + (h - HQ) * DD;
    float* base = qkv + (size_t)t * QKVSZ + colb;
    float x1 = base[j];
    float x2 = base[j + half];
    base[j]        = x1 * c - x2 * s;
    base[j + half] = x1 * s + x2 * c;
}

// ---------------- token-tiled sliding-window GQA attention ----------------
// block = (kv head, 16-token tile). 512 threads = 16 warps, one warp per token.
// K/V window UNION (144 rows) staged once; P rows are warp-private.
#define TQ 16
#define UROWS (WW + TQ)   // 144
#define KVP 68            // row pad (floats), 16B-aligned rows
#define PPAD 132
#define A_KS 0
#define A_VS (UROWS*KVP)                    // 9792
#define A_QS (2*UROWS*KVP)                  // 19584
#define A_PS (2*UROWS*KVP + TQ*GG*DD)       // 27776
#define A_FLOATS (A_PS + TQ*GG*PPAD)        // 44672
#define ATTN_SMEM (A_FLOATS*4)              // 178688 B

__global__ __launch_bounds__(512) void attn_tiled(__half* __restrict__ out_hi)
{
    extern __shared__ float sm[];
    float* Ks = sm + A_KS;
    float* Vs = sm + A_VS;
    float* Qs = sm + A_QS;
    float* Ps = sm + A_PS;

    const int kh   = blockIdx.x;
    const int tile = blockIdx.y;
    const int b    = tile >> 6;          // 64 tiles per batch
    const int i0   = (tile & 63) << 4;   // first token (seq pos) of tile
    const int tid  = threadIdx.x;
    const int warp = tid >> 5;           // local token lt
    const int lane = tid & 31;

    // ---- stage K/V union: rows u=0..143 <-> seq pos p = i0-128+u ----
    for (int idx = tid; idx < UROWS * 16; idx += 512) {
        int u = idx >> 4, d4 = (idx & 15) * 4;
        int p = i0 - WW + u;
        float4 kv = make_float4(0.f, 0.f, 0.f, 0.f);
        float4 vv = make_float4(0.f, 0.f, 0.f, 0.f);
        if (p >= 0) {
            size_t off = (size_t)(b * SS + p) * QKVSZ + QSZ + kh * DD + d4;
            kv = *(const float4*)&g_qkv[off];
            vv = *(const float4*)&g_qkv[off + KVSZ];
        }
        *(float4*)&Ks[u * KVP + d4] = kv;
        *(float4*)&Vs[u * KVP + d4] = vv;
    }
    // ---- stage Q: [lt][g][64] ----
    for (int idx = tid; idx < TQ * GG * 16; idx += 512) {
        int lt = idx >> 7, g = (idx >> 4) & 7, d4 = (idx & 15) * 4;
        size_t off = (size_t)(b * SS + i0 + lt) * QKVSZ + (kh * GG + g) * DD + d4;
        *(float4*)&Qs[(lt * GG + g) * DD + d4] = *(const float4*)&g_qkv[off];
    }
    __syncthreads();

    const int lt = warp;
    const int i  = i0 + lt;               // seq position of this warp's token
    float* prow0 = &Ps[lt * GG * PPAD];

    // ---- scores: 8 g x 129 w, lane covers w = lane + jw*32 ----
    {
        float acc[GG][4];
        #pragma unroll
        for (int g = 0; g < GG; g++)
            #pragma unroll
            for (int j = 0; j < 4; j++) acc[g][j] = 0.f;

        const float* kbase = &Ks[(lt + lane) * KVP];
        #pragma unroll
        for (int d4 = 0; d4 < DD; d4 += 4) {
            float4 k4[4];
            #pragma unroll
            for (int j = 0; j < 4; j++)
                k4[j] = *(const float4*)&kbase[j * 32 * KVP + d4];
            #pragma unroll
            for (int g = 0; g < GG; g++) {
                float4 q4 = *(const float4*)&Qs[(lt * GG + g) * DD + d4];
                #pragma unroll
                for (int j = 0; j < 4; j++) {
                    acc[g][j] += q4.x * k4[j].x + q4.y * k4[j].y
                               + q4.z * k4[j].z + q4.w * k4[j].w;
                }
            }
        }
        #pragma unroll
        for (int g = 0; g < GG; g++)
            #pragma unroll
            for (int j = 0; j < 4; j++) {
                int w = lane + j * 32;
                int p = i - WW + w;
                prow0[g * PPAD + w] = (p >= 0) ? acc[g][j] * SCALE : -1e30f;
            }
        // w = 128 column (p = i, always valid): lanes 0..7, g = lane
        if (lane < GG) {
            int g = lane;
            const float* kp = &Ks[(lt + WW) * KVP];
            const float* qp = &Qs[(lt * GG + g) * DD];
            float s = 0.f;
            #pragma unroll
            for (int d = 0; d < DD; d++) s += qp[d] * kp[d];
            prow0[g * PPAD + WW] = s * SCALE;
        }
    }
    __syncwarp();

    // ---- softmax per g row (129 entries) ----
    #pragma unroll
    for (int g = 0; g < GG; g++) {
        float* row = &prow0[g * PPAD];
        float m = -1e30f;
        for (int w = lane; w < 129; w += 32) m = fmaxf(m, row[w]);
        #pragma unroll
        for (int o = 16; o; o >>= 1) m = fmaxf(m, __shfl_xor_sync(0xffffffffu, m, o));
        float sum = 0.f;
        for (int w = lane; w < 129; w += 32) {
            float e = __expf(row[w] - m);
            row[w] = e;
            sum += e;
        }
        #pragma unroll
        for (int o = 16; o; o >>= 1) sum += __shfl_xor_sync(0xffffffffu, sum, o);
        float inv = 1.f / sum;
        for (int w = lane; w < 129; w += 32) row[w] *= inv;
    }
    __syncwarp();

    // ---- output: o[g][d] = sum_w p[g][w] * V[lt+w][d], lane owns d0=lane*2 ----
    {
        const int d0 = lane * 2;
        float acc0[GG], acc1[GG];
        #pragma unroll
        for (int g = 0; g < GG; g++) { acc0[g] = 0.f; acc1[g] = 0.f; }

        for (int wb = 0; wb < WW; wb += 4) {
            float2 v2[4];
            #pragma unroll
            for (int j = 0; j < 4; j++)
                v2[j] = *(const float2*)&Vs[(lt + wb + j) * KVP + d0];
            #pragma unroll
            for (int g = 0; g < GG; g++) {
                float4 p4 = *(const float4*)&prow0[g * PPAD + wb];
                acc0[g] += p4.x * v2[0].x + p4.y * v2[1].x + p4.z * v2[2].x + p4.w * v2[3].x;
                acc1[g] += p4.x * v2[0].y + p4.y * v2[1].y + p4.z * v2[2].y + p4.w * v2[3].y;
            }
        }
        // tail w = 128
        {
            float2 v2 = *(const float2*)&Vs[(lt + WW) * KVP + d0];
            #pragma unroll
            for (int g = 0; g < GG; g++) {
                float p = prow0[g * PPAD + WW];
                acc0[g] += p * v2.x;
                acc1[g] += p * v2.y;
            }
        }
        int t = b * SS + i;
        #pragma unroll
        for (int g = 0; g < GG; g++) {
            __half2 h2 = __floats2half2_rn(acc0[g], acc1[g]);
            *(__half2*)&out_hi[((size_t)t * HQ + kh * GG + g) * DD + d0] = h2;
        }
    }
}

// ---------------- launch ----------------
extern "C" void kernel_launch(void* const* d_in, const int* in_sizes, int n_in,
                              void* d_out, int out_size)
{
    const float* hs = (const float*)d_in[0];
    const int*  pos = (const int*)  d_in[1];
    const float* Wq = (const float*)d_in[2];
    const float* bq = (const float*)d_in[3];
    const float* Wk = (const float*)d_in[4];
    const float* bk = (const float*)d_in[5];
    const float* Wv = (const float*)d_in[6];
    const float* bv = (const float*)d_in[7];
    const float* Wo = (const float*)d_in[8];
    const float* bo = (const float*)d_in[9];
    float* out = (float*)d_out;

    __half *hs_hi, *wqkv_hi, *wqkv_lo, *wo_hi, *wo_lo, *att_hi;
    float *bqkv, *qkv;
    cudaGetSymbolAddress((void**)&hs_hi,   g_hs_hi);
    cudaGetSymbolAddress((void**)&wqkv_hi, g_Wqkv_hi);
    cudaGetSymbolAddress((void**)&wqkv_lo, g_Wqkv_lo);
    cudaGetSymbolAddress((void**)&bqkv,    g_bqkv);
    cudaGetSymbolAddress((void**)&qkv,     g_qkv);
    cudaGetSymbolAddress((void**)&wo_hi,   g_Wo_hi);
    cudaGetSymbolAddress((void**)&wo_lo,   g_Wo_lo);
    cudaGetSymbolAddress((void**)&att_hi,  g_att_hi);

    cudaFuncSetAttribute(gemm_f16split2, cudaFuncAttributeMaxDynamicSharedMemorySize, GEMM_SMEM);
    cudaFuncSetAttribute(attn_tiled, cudaFuncAttributeMaxDynamicSharedMemorySize, ATTN_SMEM);

    // (0) combined bias
    concat_bias<<<(QKVSZ + 255) / 256, 256>>>(bq, bk, bv, bqkv);
    // (1) hidden_states -> fp16 hi
    {
        int n4 = TT * HID / 4;
        convert_hi<<<(n4 + 255) / 256, 256>>>(hs, hs_hi, n4);
    }
    // (2) fused QKV weight transpose+split
    {
        dim3 blk(32, 8);
        cts_qkv<<<dim3(QKVSZ / 32, HID / 32), blk>>>(Wq, Wk, Wv, wqkv_hi, wqkv_lo);
    }
    // (3) fused QKV projection  <-- profiled slot (launch index 3)
    gemm_f16split2<<<dim3(QKVSZ / 128, TT / 128), 256, GEMM_SMEM>>>(
        hs_hi, wqkv_hi, wqkv_lo, bqkv, qkv, TT, QKVSZ, HID, OSCALE);
    // (4) Wo transpose+split (only needed before O-proj)
    {
        dim3 blk(32, 8);
        cts_wo<<<dim3(HID / 32, QSZ / 32), blk>>>(Wo, wo_hi, wo_lo);
    }
    // (5) RoPE on q + k heads
    {
        int tot = TT * (HQ + HKV) * (DD / 2);
        rope_kernel<<<(tot + 255) / 256, 256>>>(qkv, pos);
    }
    // (6) token-tiled attention
    {
        dim3 ga(HKV, TT / TQ);
        attn_tiled<<<ga, 512, ATTN_SMEM>>>(att_hi);
    }
    // (7) output projection
    gemm_f16split2<<<dim3((HID + 127) / 128, TT / 128), 256, GEMM_SMEM>>>(
        att_hi, wo_hi, wo_lo, bo, out, TT, HID, QSZ, OSCALE);
}